// round 1
// baseline (speedup 1.0000x reference)
#include <cuda_runtime.h>

#define B_ 2
#define H_ 16
#define L_ 2048
#define D_ 64
#define BH_ (B_*H_)
#define EPS_ 1e-6f

// Scratch for feature-mapped q/k (relu(X @ W)), [BH, L, D] row-major.
__device__ float g_qf[(size_t)BH_ * L_ * D_];
__device__ float g_kf[(size_t)BH_ * L_ * D_];

// ---------------------------------------------------------------------------
// Feature map: out[bh, l, e] = relu( sum_d X[bh, l, d] * W[h, d, e] )
// Grid: (L/64, BH, 2)  z=0 -> query path, z=1 -> key path. 256 threads.
// ---------------------------------------------------------------------------
__global__ __launch_bounds__(256)
void fmap_kernel(const float* __restrict__ Q, const float* __restrict__ K,
                 const float* __restrict__ Wq, const float* __restrict__ Wk)
{
    __shared__ float XT[64][68];   // transposed: XT[d][row]
    __shared__ float Ws[64][64];   // W[d][e] row-major

    const int tile = blockIdx.x;
    const int bh   = blockIdx.y;
    const int sel  = blockIdx.z;
    const int h    = bh & (H_ - 1);
    const float* __restrict__ X = sel ? K  : Q;
    const float* __restrict__ W = sel ? Wk : Wq;
    float* __restrict__ Outp    = sel ? g_kf : g_qf;

    const int tid = threadIdx.x;
    {
        const int row = tid >> 2;            // 0..63
        const int d0  = (tid & 3) << 4;      // 0,16,32,48
        const float* src  = X + ((size_t)bh * L_ + (size_t)tile * 64 + row) * D_ + d0;
        const float* wsrc = W + (size_t)h * D_ * D_ + (size_t)row * D_ + d0;
        #pragma unroll
        for (int i = 0; i < 4; i++) {
            float4 v = *(const float4*)(src + i * 4);
            XT[d0 + i*4 + 0][row] = v.x;
            XT[d0 + i*4 + 1][row] = v.y;
            XT[d0 + i*4 + 2][row] = v.z;
            XT[d0 + i*4 + 3][row] = v.w;
            *(float4*)&Ws[row][d0 + i*4] = *(const float4*)(wsrc + i * 4);
        }
    }
    __syncthreads();

    const int ty = tid >> 4, tx = tid & 15;
    float acc[4][4] = {};
    #pragma unroll 8
    for (int d = 0; d < 64; d++) {
        float4 a = *(const float4*)&XT[d][ty * 4];
        float4 b = *(const float4*)&Ws[d][tx * 4];
        float av[4] = {a.x, a.y, a.z, a.w};
        float bv[4] = {b.x, b.y, b.z, b.w};
        #pragma unroll
        for (int r = 0; r < 4; r++)
            #pragma unroll
            for (int c = 0; c < 4; c++)
                acc[r][c] = fmaf(av[r], bv[c], acc[r][c]);
    }

    float* dst = Outp + ((size_t)bh * L_ + (size_t)tile * 64 + ty * 4) * D_ + tx * 4;
    #pragma unroll
    for (int r = 0; r < 4; r++) {
        float4 v;
        v.x = fmaxf(acc[r][0], 0.f);
        v.y = fmaxf(acc[r][1], 0.f);
        v.z = fmaxf(acc[r][2], 0.f);
        v.w = fmaxf(acc[r][3], 0.f);
        *(float4*)(dst + (size_t)r * D_) = v;
    }
}

// ---------------------------------------------------------------------------
// Streaming causal attention over 64x64 tiles.
// Grid: (L/64 = 32 query tiles, BH = 32). 256 threads, 4x4 micro-tiles.
// Dynamic smem: qT/kT/Vs/Ss each [64][68] + rowsum[64]  (~70 KB).
// ---------------------------------------------------------------------------
__global__ __launch_bounds__(256)
void attn_kernel(const float* __restrict__ Vp, float* __restrict__ Outp)
{
    extern __shared__ float sm[];
    float (*qT)[68] = (float(*)[68])(sm);                 // qT[d][row]
    float (*kT)[68] = (float(*)[68])(sm + 64 * 68);       // kT[d][col]
    float (*Vs)[68] = (float(*)[68])(sm + 2 * 64 * 68);   // Vs[n][dv]
    float (*Ss)[68] = (float(*)[68])(sm + 3 * 64 * 68);   // Ss[row][n]
    float* rowsum   = sm + 4 * 64 * 68;                   // [64]

    const int qi  = blockIdx.x;
    const int bh  = blockIdx.y;
    const int tid = threadIdx.x;
    const int ty = tid >> 4, tx = tid & 15;
    const int lrow = tid >> 2;
    const int ld0  = (tid & 3) << 4;

    // Load query tile (transposed) once.
    {
        const float* src = g_qf + ((size_t)bh * L_ + (size_t)qi * 64 + lrow) * D_ + ld0;
        #pragma unroll
        for (int i = 0; i < 4; i++) {
            float4 v = *(const float4*)(src + i * 4);
            qT[ld0 + i*4 + 0][lrow] = v.x;
            qT[ld0 + i*4 + 1][lrow] = v.y;
            qT[ld0 + i*4 + 2][lrow] = v.z;
            qT[ld0 + i*4 + 3][lrow] = v.w;
        }
    }
    if (tid < 64) rowsum[tid] = 0.f;

    float o[4][4] = {};

    for (int j = 0; j <= qi; j++) {
        __syncthreads();  // prior iteration's Ss/Vs reads done; also covers qT/rowsum init
        {
            const float* ksrc = g_kf + ((size_t)bh * L_ + (size_t)j * 64 + lrow) * D_ + ld0;
            const float* vsrc = Vp   + ((size_t)bh * L_ + (size_t)j * 64 + lrow) * D_ + ld0;
            #pragma unroll
            for (int i = 0; i < 4; i++) {
                float4 v = *(const float4*)(ksrc + i * 4);
                kT[ld0 + i*4 + 0][lrow] = v.x;
                kT[ld0 + i*4 + 1][lrow] = v.y;
                kT[ld0 + i*4 + 2][lrow] = v.z;
                kT[ld0 + i*4 + 3][lrow] = v.w;
                *(float4*)&Vs[lrow][ld0 + i*4] = *(const float4*)(vsrc + i * 4);
            }
        }
        __syncthreads();

        // S = q k^T  (feature-mapped, so S >= 0)
        float s[4][4] = {};
        #pragma unroll 8
        for (int d = 0; d < 64; d++) {
            float4 a = *(const float4*)&qT[d][ty * 4];
            float4 b = *(const float4*)&kT[d][tx * 4];
            float av[4] = {a.x, a.y, a.z, a.w};
            float bv[4] = {b.x, b.y, b.z, b.w};
            #pragma unroll
            for (int r = 0; r < 4; r++)
                #pragma unroll
                for (int c = 0; c < 4; c++)
                    s[r][c] = fmaf(av[r], bv[c], s[r][c]);
        }

        if (j == qi) {  // causal mask on diagonal tile (keep col <= row)
            #pragma unroll
            for (int r = 0; r < 4; r++)
                #pragma unroll
                for (int c = 0; c < 4; c++)
                    if (tx * 4 + c > ty * 4 + r) s[r][c] = 0.f;
        }

        // Store S tile + accumulate row sums (reduce across the 16 tx lanes).
        #pragma unroll
        for (int r = 0; r < 4; r++) {
            *(float4*)&Ss[ty * 4 + r][tx * 4] =
                make_float4(s[r][0], s[r][1], s[r][2], s[r][3]);
            float p = (s[r][0] + s[r][1]) + (s[r][2] + s[r][3]);
            p += __shfl_xor_sync(0xffffffffu, p, 1);
            p += __shfl_xor_sync(0xffffffffu, p, 2);
            p += __shfl_xor_sync(0xffffffffu, p, 4);
            p += __shfl_xor_sync(0xffffffffu, p, 8);
            if (tx == 0) rowsum[ty * 4 + r] += p;
        }
        __syncthreads();

        // O += S @ V
        #pragma unroll 8
        for (int n = 0; n < 64; n++) {
            float4 vv = *(const float4*)&Vs[n][tx * 4];
            float s0 = Ss[ty * 4 + 0][n];
            float s1 = Ss[ty * 4 + 1][n];
            float s2 = Ss[ty * 4 + 2][n];
            float s3 = Ss[ty * 4 + 3][n];
            o[0][0] = fmaf(s0, vv.x, o[0][0]); o[0][1] = fmaf(s0, vv.y, o[0][1]);
            o[0][2] = fmaf(s0, vv.z, o[0][2]); o[0][3] = fmaf(s0, vv.w, o[0][3]);
            o[1][0] = fmaf(s1, vv.x, o[1][0]); o[1][1] = fmaf(s1, vv.y, o[1][1]);
            o[1][2] = fmaf(s1, vv.z, o[1][2]); o[1][3] = fmaf(s1, vv.w, o[1][3]);
            o[2][0] = fmaf(s2, vv.x, o[2][0]); o[2][1] = fmaf(s2, vv.y, o[2][1]);
            o[2][2] = fmaf(s2, vv.z, o[2][2]); o[2][3] = fmaf(s2, vv.w, o[2][3]);
            o[3][0] = fmaf(s3, vv.x, o[3][0]); o[3][1] = fmaf(s3, vv.y, o[3][1]);
            o[3][2] = fmaf(s3, vv.z, o[3][2]); o[3][3] = fmaf(s3, vv.w, o[3][3]);
        }
    }
    __syncthreads();  // all rowsum contributions visible

    #pragma unroll
    for (int r = 0; r < 4; r++) {
        float inv = 1.0f / (rowsum[ty * 4 + r] + EPS_);
        float4 v = make_float4(o[r][0] * inv, o[r][1] * inv,
                               o[r][2] * inv, o[r][3] * inv);
        *(float4*)(Outp + ((size_t)bh * L_ + (size_t)qi * 64 + ty * 4 + r) * D_ + tx * 4) = v;
    }
}

// ---------------------------------------------------------------------------
extern "C" void kernel_launch(void* const* d_in, const int* in_sizes, int n_in,
                              void* d_out, int out_size)
{
    (void)in_sizes; (void)n_in; (void)out_size;
    const float* Q  = (const float*)d_in[0];
    const float* K  = (const float*)d_in[1];
    const float* V  = (const float*)d_in[2];
    const float* Wq = (const float*)d_in[3];
    const float* Wk = (const float*)d_in[4];
    float* Out = (float*)d_out;

    const int attn_smem = (4 * 64 * 68 + 64) * (int)sizeof(float);  // ~69.9 KB
    cudaFuncSetAttribute(attn_kernel,
                         cudaFuncAttributeMaxDynamicSharedMemorySize, attn_smem);

    dim3 fgrid(L_ / 64, BH_, 2);
    fmap_kernel<<<fgrid, 256>>>(Q, K, Wq, Wk);

    dim3 agrid(L_ / 64, BH_);
    attn_kernel<<<agrid, 256, attn_smem>>>(V, Out);
}

// round 3
// speedup vs baseline: 5.4187x; 5.4187x over previous
#include <cuda_runtime.h>
#include <cstdint>

#define B_ 2
#define H_ 16
#define L_ 2048
#define D_ 64
#define BH_ (B_*H_)
#define NC_ 32            // chunks per bh (chunk = 64 rows)
#define EPS_ 1e-6f

// Scratch (device globals; allocation-free rule).
__device__ float g_qf[(size_t)BH_ * L_ * D_];            // relu(Q @ Wq)
__device__ float g_kf[(size_t)BH_ * L_ * D_];            // relu(K @ Wk)
__device__ float g_kv[(size_t)BH_ * NC_ * D_ * D_];      // per-chunk Kf^T V
__device__ float g_state[(size_t)BH_ * NC_ * D_ * D_];   // exclusive prefix of g_kv
__device__ float g_ks[(size_t)BH_ * NC_ * D_];           // per-chunk sum of kf
__device__ float g_zs[(size_t)BH_ * NC_ * D_];           // exclusive prefix of g_ks

// ===========================================================================
// Feature map: out[bh,l,e] = relu( sum_d X[bh,l,d] * W[h,d,e] )
// Grid (L/64, BH, 2); 256 threads; 4x4 micro-tiles.
// ===========================================================================
__global__ __launch_bounds__(256)
void fmap_kernel(const float* __restrict__ Q, const float* __restrict__ K,
                 const float* __restrict__ Wq, const float* __restrict__ Wk)
{
    __shared__ float XT[64][68];   // XT[d][row]
    __shared__ float Ws[64][68];   // W[d][e]

    const int tile = blockIdx.x, bh = blockIdx.y, sel = blockIdx.z;
    const int h = bh & (H_ - 1);
    const float* __restrict__ X = sel ? K : Q;
    const float* __restrict__ W = sel ? Wk : Wq;
    float* __restrict__ Outp = sel ? g_kf : g_qf;

    const int tid = threadIdx.x;
    {
        const int row = tid >> 2, d0 = (tid & 3) << 4;
        const float* src  = X + ((size_t)bh * L_ + (size_t)tile * 64 + row) * D_ + d0;
        const float* wsrc = W + (size_t)h * D_ * D_ + (size_t)row * D_ + d0;
        #pragma unroll
        for (int i = 0; i < 4; i++) {
            float4 v = *(const float4*)(src + i * 4);
            XT[d0 + i*4 + 0][row] = v.x; XT[d0 + i*4 + 1][row] = v.y;
            XT[d0 + i*4 + 2][row] = v.z; XT[d0 + i*4 + 3][row] = v.w;
            *(float4*)&Ws[row][d0 + i*4] = *(const float4*)(wsrc + i * 4);
        }
    }
    __syncthreads();

    const int ty = tid >> 4, tx = tid & 15;
    float acc[4][4] = {};
    #pragma unroll 8
    for (int d = 0; d < 64; d++) {
        float4 a = *(const float4*)&XT[d][ty * 4];
        float4 b = *(const float4*)&Ws[d][tx * 4];
        float av[4] = {a.x, a.y, a.z, a.w};
        float bv[4] = {b.x, b.y, b.z, b.w};
        #pragma unroll
        for (int r = 0; r < 4; r++)
            #pragma unroll
            for (int c = 0; c < 4; c++)
                acc[r][c] = fmaf(av[r], bv[c], acc[r][c]);
    }

    float* dst = Outp + ((size_t)bh * L_ + (size_t)tile * 64 + ty * 4) * D_ + tx * 4;
    #pragma unroll
    for (int r = 0; r < 4; r++) {
        float4 v;
        v.x = fmaxf(acc[r][0], 0.f); v.y = fmaxf(acc[r][1], 0.f);
        v.z = fmaxf(acc[r][2], 0.f); v.w = fmaxf(acc[r][3], 0.f);
        *(float4*)(dst + (size_t)r * D_) = v;
    }
}

// ===========================================================================
// Per-chunk KV = Kf_c^T @ V_c  (64x64) and ksum_c[d] = sum_n kf[n][d].
// Grid (NC, BH); 256 threads.
// ===========================================================================
__global__ __launch_bounds__(256)
void kv_kernel(const float* __restrict__ V)
{
    __shared__ float Ks[64][68];   // [n][d]
    __shared__ float Vs[64][68];   // [n][e]

    const int c = blockIdx.x, bh = blockIdx.y;
    const int tid = threadIdx.x;
    const size_t rowbase = (size_t)bh * L_ + (size_t)c * 64;

    {
        const int row = tid >> 2, d0 = (tid & 3) << 4;
        const float* ks = g_kf + (rowbase + row) * D_ + d0;
        const float* vs = V    + (rowbase + row) * D_ + d0;
        #pragma unroll
        for (int i = 0; i < 4; i++) {
            *(float4*)&Ks[row][d0 + i*4] = *(const float4*)(ks + i * 4);
            *(float4*)&Vs[row][d0 + i*4] = *(const float4*)(vs + i * 4);
        }
    }
    __syncthreads();

    const int ty = tid >> 4, tx = tid & 15;
    float acc[4][4] = {};
    #pragma unroll 8
    for (int n = 0; n < 64; n++) {
        float4 a = *(const float4*)&Ks[n][ty * 4];   // kf[n][d block]
        float4 b = *(const float4*)&Vs[n][tx * 4];   // v[n][e block]
        float av[4] = {a.x, a.y, a.z, a.w};
        float bv[4] = {b.x, b.y, b.z, b.w};
        #pragma unroll
        for (int r = 0; r < 4; r++)
            #pragma unroll
            for (int cc = 0; cc < 4; cc++)
                acc[r][cc] = fmaf(av[r], bv[cc], acc[r][cc]);
    }

    float* kvdst = g_kv + ((size_t)(bh * NC_ + c) * D_ + ty * 4) * D_ + tx * 4;
    #pragma unroll
    for (int r = 0; r < 4; r++)
        *(float4*)(kvdst + (size_t)r * D_) =
            make_float4(acc[r][0], acc[r][1], acc[r][2], acc[r][3]);

    if (tid < 64) {
        float s = 0.f;
        #pragma unroll 8
        for (int n = 0; n < 64; n++) s += Ks[n][tid];
        g_ks[(size_t)(bh * NC_ + c) * D_ + tid] = s;
    }
}

// ===========================================================================
// Exclusive prefix scan over chunks (per bh, per element).
// Grid (17, BH): x<16 -> 256 KV elements each; x==16 -> the 64 z elements.
// ===========================================================================
__global__ __launch_bounds__(256)
void scan_kernel()
{
    const int g = blockIdx.x, bh = blockIdx.y, tid = threadIdx.x;
    if (g < 16) {
        const int e = g * 256 + tid;             // 0..4095
        float acc = 0.f;
        #pragma unroll
        for (int c = 0; c < NC_; c++) {
            const size_t idx = (size_t)(bh * NC_ + c) * (D_ * D_) + e;
            g_state[idx] = acc;
            acc += g_kv[idx];
        }
    } else if (tid < 64) {
        float acc = 0.f;
        #pragma unroll
        for (int c = 0; c < NC_; c++) {
            const size_t idx = (size_t)(bh * NC_ + c) * D_ + tid;
            g_zs[idx] = acc;
            acc += g_ks[idx];
        }
    }
}

// ===========================================================================
// Per-chunk output:
//   S = tril(Qf_c @ Kf_c^T)            (64x64, intra-chunk)
//   O = S @ V_c + Qf_c @ state_c       ; denom = rowsum(S) + qf . z_c + EPS
// Grid (NC, BH); 256 threads; ~88 KB dynamic smem.
// ===========================================================================
__global__ __launch_bounds__(256)
void out_kernel(const float* __restrict__ V, float* __restrict__ Out)
{
    extern __shared__ float sm[];
    float (*qT)[68]  = (float(*)[68])(sm);                 // qT[d][m]
    float (*kT)[68]  = (float(*)[68])(sm + 1 * 64 * 68);   // kT[d][n]
    float (*Vs)[68]  = (float(*)[68])(sm + 2 * 64 * 68);   // Vs[n][e]
    float (*Sts)[68] = (float(*)[68])(sm + 3 * 64 * 68);   // state[d][e]
    float (*St)[68]  = (float(*)[68])(sm + 4 * 64 * 68);   // S^T: St[n][m]
    float* rowsum    = sm + 5 * 64 * 68;                   // [64]
    float* qz        = rowsum + 64;                        // [64]
    float* zs        = qz + 64;                            // [64]

    const int c = blockIdx.x, bh = blockIdx.y;
    const int tid = threadIdx.x;
    const int ty = tid >> 4, tx = tid & 15;
    const size_t rowbase = (size_t)bh * L_ + (size_t)c * 64;
    const size_t chunk = (size_t)(bh * NC_ + c);

    {
        const int row = tid >> 2, d0 = (tid & 3) << 4;
        const float* qs = g_qf + (rowbase + row) * D_ + d0;
        const float* ks = g_kf + (rowbase + row) * D_ + d0;
        const float* vs = V    + (rowbase + row) * D_ + d0;
        const float* ss = g_state + (chunk * D_ + row) * D_ + d0;
        #pragma unroll
        for (int i = 0; i < 4; i++) {
            float4 q4 = *(const float4*)(qs + i * 4);
            qT[d0 + i*4 + 0][row] = q4.x; qT[d0 + i*4 + 1][row] = q4.y;
            qT[d0 + i*4 + 2][row] = q4.z; qT[d0 + i*4 + 3][row] = q4.w;
            float4 k4 = *(const float4*)(ks + i * 4);
            kT[d0 + i*4 + 0][row] = k4.x; kT[d0 + i*4 + 1][row] = k4.y;
            kT[d0 + i*4 + 2][row] = k4.z; kT[d0 + i*4 + 3][row] = k4.w;
            *(float4*)&Vs[row][d0 + i*4]  = *(const float4*)(vs + i * 4);
            *(float4*)&Sts[row][d0 + i*4] = *(const float4*)(ss + i * 4);
        }
        if (tid < 64) zs[tid] = g_zs[chunk * D_ + tid];
    }
    __syncthreads();

    // ---- S = tril(Qf Kf^T), stored transposed; rowsum via shfl ----
    float s[4][4] = {};
    #pragma unroll 8
    for (int d = 0; d < 64; d++) {
        float4 a = *(const float4*)&qT[d][ty * 4];
        float4 b = *(const float4*)&kT[d][tx * 4];
        float av[4] = {a.x, a.y, a.z, a.w};
        float bv[4] = {b.x, b.y, b.z, b.w};
        #pragma unroll
        for (int r = 0; r < 4; r++)
            #pragma unroll
            for (int cc = 0; cc < 4; cc++)
                s[r][cc] = fmaf(av[r], bv[cc], s[r][cc]);
    }
    #pragma unroll
    for (int r = 0; r < 4; r++)
        #pragma unroll
        for (int cc = 0; cc < 4; cc++)
            if (tx * 4 + cc > ty * 4 + r) s[r][cc] = 0.f;   // causal within chunk

    #pragma unroll
    for (int cc = 0; cc < 4; cc++)
        *(float4*)&St[tx * 4 + cc][ty * 4] =
            make_float4(s[0][cc], s[1][cc], s[2][cc], s[3][cc]);

    #pragma unroll
    for (int r = 0; r < 4; r++) {
        float p = (s[r][0] + s[r][1]) + (s[r][2] + s[r][3]);
        p += __shfl_xor_sync(0xffffffffu, p, 1);
        p += __shfl_xor_sync(0xffffffffu, p, 2);
        p += __shfl_xor_sync(0xffffffffu, p, 4);
        p += __shfl_xor_sync(0xffffffffu, p, 8);
        if (tx == 0) rowsum[ty * 4 + r] = p;
    }

    if (tid < 64) {   // qz[m] = qf[m] . z_prev
        float acc = 0.f;
        #pragma unroll 8
        for (int d = 0; d < 64; d++) acc = fmaf(qT[d][tid], zs[d], acc);
        qz[tid] = acc;
    }
    __syncthreads();

    // ---- O = S @ V + Qf @ state ----
    float o[4][4] = {};
    #pragma unroll 8
    for (int n = 0; n < 64; n++) {
        float4 a = *(const float4*)&St[n][ty * 4];   // S[m block][n]
        float4 b = *(const float4*)&Vs[n][tx * 4];
        float av[4] = {a.x, a.y, a.z, a.w};
        float bv[4] = {b.x, b.y, b.z, b.w};
        #pragma unroll
        for (int r = 0; r < 4; r++)
            #pragma unroll
            for (int cc = 0; cc < 4; cc++)
                o[r][cc] = fmaf(av[r], bv[cc], o[r][cc]);
    }
    #pragma unroll 8
    for (int d = 0; d < 64; d++) {
        float4 a = *(const float4*)&qT[d][ty * 4];
        float4 b = *(const float4*)&Sts[d][tx * 4];
        float av[4] = {a.x, a.y, a.z, a.w};
        float bv[4] = {b.x, b.y, b.z, b.w};
        #pragma unroll
        for (int r = 0; r < 4; r++)
            #pragma unroll
            for (int cc = 0; cc < 4; cc++)
                o[r][cc] = fmaf(av[r], bv[cc], o[r][cc]);
    }

    float* dst = Out + (rowbase + ty * 4) * D_ + tx * 4;
    #pragma unroll
    for (int r = 0; r < 4; r++) {
        const float inv = 1.0f / (rowsum[ty * 4 + r] + qz[ty * 4 + r] + EPS_);
        *(float4*)(dst + (size_t)r * D_) =
            make_float4(o[r][0] * inv, o[r][1] * inv, o[r][2] * inv, o[r][3] * inv);
    }
}

// ===========================================================================
extern "C" void kernel_launch(void* const* d_in, const int* in_sizes, int n_in,
                              void* d_out, int out_size)
{
    (void)in_sizes; (void)n_in; (void)out_size;
    const float* Q  = (const float*)d_in[0];
    const float* K  = (const float*)d_in[1];
    const float* V  = (const float*)d_in[2];
    const float* Wq = (const float*)d_in[3];
    const float* Wk = (const float*)d_in[4];
    float* Out = (float*)d_out;

    const int out_smem = (5 * 64 * 68 + 192) * (int)sizeof(float);  // ~87.8 KB
    cudaFuncSetAttribute(out_kernel,
                         cudaFuncAttributeMaxDynamicSharedMemorySize, out_smem);

    fmap_kernel<<<dim3(L_ / 64, BH_, 2), 256>>>(Q, K, Wq, Wk);
    kv_kernel<<<dim3(NC_, BH_), 256>>>(V);
    scan_kernel<<<dim3(17, BH_), 256>>>();
    out_kernel<<<dim3(NC_, BH_), 256, out_smem>>>(V, Out);
}

// round 4
// speedup vs baseline: 5.8522x; 1.0800x over previous
#include <cuda_runtime.h>
#include <cstdint>

#define B_ 2
#define H_ 16
#define L_ 2048
#define D_ 64
#define BH_ (B_*H_)
#define NC_ 32            // chunks per bh (chunk = 64 rows)
#define EPS_ 1e-6f

// Scratch (device globals; allocation-free rule).
__device__ float g_qf[(size_t)BH_ * L_ * D_];            // relu(Q @ Wq)
__device__ float g_kf[(size_t)BH_ * L_ * D_];            // relu(K @ Wk)
__device__ float g_kv[(size_t)BH_ * NC_ * D_ * D_];      // per-chunk Kf^T V
__device__ float g_state[(size_t)BH_ * NC_ * D_ * D_];   // exclusive prefix of g_kv
__device__ float g_ks[(size_t)BH_ * NC_ * D_];           // per-chunk sum of kf
__device__ float g_zs[(size_t)BH_ * NC_ * D_];           // exclusive prefix of g_ks

// ===========================================================================
// Fused feature map + (key path only) chunk KV/ksum.
//   out[bh,l,e] = relu( sum_d X[bh,l,d] * W[h,d,e] )
//   sel==1 additionally: KV_c = Kf_c^T @ V_c ; ksum_c = sum_n kf_c[n]
// Grid (L/64, BH, 2); 256 threads; 4x4 micro-tiles.
// ===========================================================================
__global__ __launch_bounds__(256)
void fmap_kernel(const float* __restrict__ Q, const float* __restrict__ K,
                 const float* __restrict__ V,
                 const float* __restrict__ Wq, const float* __restrict__ Wk)
{
    __shared__ float XT[64][68];   // XT[d][row]   (later: Ks[n][e])
    __shared__ float Ws[64][68];   // W[d][e]      (later: Vs[n][e])

    const int tile = blockIdx.x, bh = blockIdx.y, sel = blockIdx.z;
    const int h = bh & (H_ - 1);
    const float* __restrict__ X = sel ? K : Q;
    const float* __restrict__ W = sel ? Wk : Wq;
    float* __restrict__ Outp = sel ? g_kf : g_qf;

    const int tid = threadIdx.x;
    const int row = tid >> 2, d0 = (tid & 3) << 4;
    const size_t rowbase = (size_t)bh * L_ + (size_t)tile * 64;
    {
        const float* src  = X + (rowbase + row) * D_ + d0;
        const float* wsrc = W + (size_t)h * D_ * D_ + (size_t)row * D_ + d0;
        #pragma unroll
        for (int i = 0; i < 4; i++) {
            float4 v = *(const float4*)(src + i * 4);
            XT[d0 + i*4 + 0][row] = v.x; XT[d0 + i*4 + 1][row] = v.y;
            XT[d0 + i*4 + 2][row] = v.z; XT[d0 + i*4 + 3][row] = v.w;
            *(float4*)&Ws[row][d0 + i*4] = *(const float4*)(wsrc + i * 4);
        }
    }
    __syncthreads();

    const int ty = tid >> 4, tx = tid & 15;
    float acc[4][4] = {};
    #pragma unroll 8
    for (int d = 0; d < 64; d++) {
        float4 a = *(const float4*)&XT[d][ty * 4];
        float4 b = *(const float4*)&Ws[d][tx * 4];
        float av[4] = {a.x, a.y, a.z, a.w};
        float bv[4] = {b.x, b.y, b.z, b.w};
        #pragma unroll
        for (int r = 0; r < 4; r++)
            #pragma unroll
            for (int c = 0; c < 4; c++)
                acc[r][c] = fmaf(av[r], bv[c], acc[r][c]);
    }
    #pragma unroll
    for (int r = 0; r < 4; r++)
        #pragma unroll
        for (int c = 0; c < 4; c++)
            acc[r][c] = fmaxf(acc[r][c], 0.f);

    float* dst = Outp + (rowbase + ty * 4) * D_ + tx * 4;
    #pragma unroll
    for (int r = 0; r < 4; r++)
        *(float4*)(dst + (size_t)r * D_) =
            make_float4(acc[r][0], acc[r][1], acc[r][2], acc[r][3]);

    if (!sel) return;

    // ---- key path: reuse smem for KV = Kf^T @ V and ksum ----
    __syncthreads();   // XT/Ws reads done
    float (*Ks)[68] = XT;   // Ks[n][e] = kf tile
    float (*Vs)[68] = Ws;   // Vs[n][e'] = V tile
    #pragma unroll
    for (int r = 0; r < 4; r++)
        *(float4*)&Ks[ty * 4 + r][tx * 4] =
            make_float4(acc[r][0], acc[r][1], acc[r][2], acc[r][3]);
    {
        const float* vs = V + (rowbase + row) * D_ + d0;
        #pragma unroll
        for (int i = 0; i < 4; i++)
            *(float4*)&Vs[row][d0 + i*4] = *(const float4*)(vs + i * 4);
    }
    __syncthreads();

    float kv[4][4] = {};
    #pragma unroll 8
    for (int n = 0; n < 64; n++) {
        float4 a = *(const float4*)&Ks[n][ty * 4];
        float4 b = *(const float4*)&Vs[n][tx * 4];
        float av[4] = {a.x, a.y, a.z, a.w};
        float bv[4] = {b.x, b.y, b.z, b.w};
        #pragma unroll
        for (int r = 0; r < 4; r++)
            #pragma unroll
            for (int c = 0; c < 4; c++)
                kv[r][c] = fmaf(av[r], bv[c], kv[r][c]);
    }

    float* kvdst = g_kv + ((size_t)(bh * NC_ + tile) * D_ + ty * 4) * D_ + tx * 4;
    #pragma unroll
    for (int r = 0; r < 4; r++)
        *(float4*)(kvdst + (size_t)r * D_) =
            make_float4(kv[r][0], kv[r][1], kv[r][2], kv[r][3]);

    if (tid < 64) {
        float s = 0.f;
        #pragma unroll 8
        for (int n = 0; n < 64; n++) s += Ks[n][tid];
        g_ks[(size_t)(bh * NC_ + tile) * D_ + tid] = s;
    }
}

// ===========================================================================
// Exclusive prefix scan over chunks (per bh, per element).
// Grid (17, BH): x<16 -> 256 KV elements each; x==16 -> the 64 z elements.
// ===========================================================================
__global__ __launch_bounds__(256)
void scan_kernel()
{
    const int g = blockIdx.x, bh = blockIdx.y, tid = threadIdx.x;
    if (g < 16) {
        const int e = g * 256 + tid;             // 0..4095
        float acc = 0.f;
        #pragma unroll
        for (int c = 0; c < NC_; c++) {
            const size_t idx = (size_t)(bh * NC_ + c) * (D_ * D_) + e;
            g_state[idx] = acc;
            acc += g_kv[idx];
        }
    } else if (tid < 64) {
        float acc = 0.f;
        #pragma unroll
        for (int c = 0; c < NC_; c++) {
            const size_t idx = (size_t)(bh * NC_ + c) * D_ + tid;
            g_zs[idx] = acc;
            acc += g_ks[idx];
        }
    }
}

// ===========================================================================
// Per-chunk output:
//   S = tril(Qf_c @ Kf_c^T)            (64x64, intra-chunk)
//   O = S @ V_c + Qf_c @ state_c       ; denom = rowsum(S) + qf . z_c + EPS
// Grid (NC, BH); 256 threads; 70.4 KB dynamic smem (4 buffers; kT reused as S^T)
// ===========================================================================
__global__ __launch_bounds__(256, 3)
void out_kernel(const float* __restrict__ V, float* __restrict__ Out)
{
    extern __shared__ float sm[];
    float (*qT)[68]  = (float(*)[68])(sm);                 // qT[d][m]
    float (*kT)[68]  = (float(*)[68])(sm + 1 * 64 * 68);   // kT[d][n] -> St[n][m]
    float (*Vs)[68]  = (float(*)[68])(sm + 2 * 64 * 68);   // Vs[n][e]
    float (*Sts)[68] = (float(*)[68])(sm + 3 * 64 * 68);   // state[d][e]
    float* rowsum    = sm + 4 * 64 * 68;                   // [64]
    float* qz        = rowsum + 64;                        // [64]
    float* zs        = qz + 64;                            // [64]

    const int c = blockIdx.x, bh = blockIdx.y;
    const int tid = threadIdx.x;
    const int ty = tid >> 4, tx = tid & 15;
    const size_t rowbase = (size_t)bh * L_ + (size_t)c * 64;
    const size_t chunk = (size_t)(bh * NC_ + c);

    {
        const int row = tid >> 2, d0 = (tid & 3) << 4;
        const float* qs = g_qf + (rowbase + row) * D_ + d0;
        const float* ks = g_kf + (rowbase + row) * D_ + d0;
        const float* vs = V    + (rowbase + row) * D_ + d0;
        const float* ss = g_state + (chunk * D_ + row) * D_ + d0;
        #pragma unroll
        for (int i = 0; i < 4; i++) {
            float4 q4 = *(const float4*)(qs + i * 4);
            qT[d0 + i*4 + 0][row] = q4.x; qT[d0 + i*4 + 1][row] = q4.y;
            qT[d0 + i*4 + 2][row] = q4.z; qT[d0 + i*4 + 3][row] = q4.w;
            float4 k4 = *(const float4*)(ks + i * 4);
            kT[d0 + i*4 + 0][row] = k4.x; kT[d0 + i*4 + 1][row] = k4.y;
            kT[d0 + i*4 + 2][row] = k4.z; kT[d0 + i*4 + 3][row] = k4.w;
            *(float4*)&Vs[row][d0 + i*4]  = *(const float4*)(vs + i * 4);
            *(float4*)&Sts[row][d0 + i*4] = *(const float4*)(ss + i * 4);
        }
        if (tid < 64) zs[tid] = g_zs[chunk * D_ + tid];
    }
    __syncthreads();

    // ---- S = tril(Qf Kf^T); rowsum via shfl; qz = qf . z_prev ----
    float s[4][4] = {};
    #pragma unroll 8
    for (int d = 0; d < 64; d++) {
        float4 a = *(const float4*)&qT[d][ty * 4];
        float4 b = *(const float4*)&kT[d][tx * 4];
        float av[4] = {a.x, a.y, a.z, a.w};
        float bv[4] = {b.x, b.y, b.z, b.w};
        #pragma unroll
        for (int r = 0; r < 4; r++)
            #pragma unroll
            for (int cc = 0; cc < 4; cc++)
                s[r][cc] = fmaf(av[r], bv[cc], s[r][cc]);
    }
    #pragma unroll
    for (int r = 0; r < 4; r++)
        #pragma unroll
        for (int cc = 0; cc < 4; cc++)
            if (tx * 4 + cc > ty * 4 + r) s[r][cc] = 0.f;   // causal within chunk

    #pragma unroll
    for (int r = 0; r < 4; r++) {
        float p = (s[r][0] + s[r][1]) + (s[r][2] + s[r][3]);
        p += __shfl_xor_sync(0xffffffffu, p, 1);
        p += __shfl_xor_sync(0xffffffffu, p, 2);
        p += __shfl_xor_sync(0xffffffffu, p, 4);
        p += __shfl_xor_sync(0xffffffffu, p, 8);
        if (tx == 0) rowsum[ty * 4 + r] = p;
    }
    if (tid < 64) {
        float acc = 0.f;
        #pragma unroll 8
        for (int d = 0; d < 64; d++) acc = fmaf(qT[d][tid], zs[d], acc);
        qz[tid] = acc;
    }

    __syncthreads();   // all kT reads done; safe to overwrite with S^T
    float (*St)[68] = kT;   // St[n][m]
    #pragma unroll
    for (int cc = 0; cc < 4; cc++)
        *(float4*)&St[tx * 4 + cc][ty * 4] =
            make_float4(s[0][cc], s[1][cc], s[2][cc], s[3][cc]);
    __syncthreads();

    // ---- O = S @ V + Qf @ state ----
    float o[4][4] = {};
    #pragma unroll 8
    for (int n = 0; n < 64; n++) {
        float4 a = *(const float4*)&St[n][ty * 4];   // S[m block][n]
        float4 b = *(const float4*)&Vs[n][tx * 4];
        float av[4] = {a.x, a.y, a.z, a.w};
        float bv[4] = {b.x, b.y, b.z, b.w};
        #pragma unroll
        for (int r = 0; r < 4; r++)
            #pragma unroll
            for (int cc = 0; cc < 4; cc++)
                o[r][cc] = fmaf(av[r], bv[cc], o[r][cc]);
    }
    #pragma unroll 8
    for (int d = 0; d < 64; d++) {
        float4 a = *(const float4*)&qT[d][ty * 4];
        float4 b = *(const float4*)&Sts[d][tx * 4];
        float av[4] = {a.x, a.y, a.z, a.w};
        float bv[4] = {b.x, b.y, b.z, b.w};
        #pragma unroll
        for (int r = 0; r < 4; r++)
            #pragma unroll
            for (int cc = 0; cc < 4; cc++)
                o[r][cc] = fmaf(av[r], bv[cc], o[r][cc]);
    }

    float* dst = Out + (rowbase + ty * 4) * D_ + tx * 4;
    #pragma unroll
    for (int r = 0; r < 4; r++) {
        const float inv = 1.0f / (rowsum[ty * 4 + r] + qz[ty * 4 + r] + EPS_);
        *(float4*)(dst + (size_t)r * D_) =
            make_float4(o[r][0] * inv, o[r][1] * inv, o[r][2] * inv, o[r][3] * inv);
    }
}

// ===========================================================================
extern "C" void kernel_launch(void* const* d_in, const int* in_sizes, int n_in,
                              void* d_out, int out_size)
{
    (void)in_sizes; (void)n_in; (void)out_size;
    const float* Q  = (const float*)d_in[0];
    const float* K  = (const float*)d_in[1];
    const float* V  = (const float*)d_in[2];
    const float* Wq = (const float*)d_in[3];
    const float* Wk = (const float*)d_in[4];
    float* Out = (float*)d_out;

    const int out_smem = (4 * 64 * 68 + 192) * (int)sizeof(float);  // 70400 B
    cudaFuncSetAttribute(out_kernel,
                         cudaFuncAttributeMaxDynamicSharedMemorySize, out_smem);

    fmap_kernel<<<dim3(L_ / 64, BH_, 2), 256>>>(Q, K, V, Wq, Wk);
    scan_kernel<<<dim3(17, BH_), 256>>>();
    out_kernel<<<dim3(NC_, BH_), 256, out_smem>>>(V, Out);
}